// round 2
// baseline (speedup 1.0000x reference)
#include <cuda_runtime.h>

// CNN char conv + max-pool over word length.
// x: (N=B*S, W=20, E=128) fp32, contiguous.
// conv: 5-tap FIR along W with zero pad 2, + bias, then max over W.
// out: (N, E) fp32.
//
// Mapping: 32 threads per word along E (float4 each). Pure HBM stream,
// MLP=20 per thread, fully unrolled compile-time window.

#define WLEN 20
#define EV4  32   // 128 floats / 4 per float4

__global__ __launch_bounds__(256) void cnn_conv_max_kernel(
    const float* __restrict__ x,
    const float* __restrict__ w,
    const float* __restrict__ b,
    float* __restrict__ out,
    int n_words)
{
    int tid    = blockIdx.x * blockDim.x + threadIdx.x;
    int lane_e = tid & (EV4 - 1);
    int word   = tid >> 5;
    if (word >= n_words) return;

    const float4* xw = reinterpret_cast<const float4*>(x)
                     + (size_t)word * (WLEN * EV4) + lane_e;

    // Weights/bias: 6 scalar loads, L1-resident after first warp.
    float w0 = w[0], w1 = w[1], w2 = w[2], w3 = w[3], w4 = w[4];
    float bias = b[0];

    // Front-batched loads: 20 independent float4 -> MLP=20.
    float4 xv[WLEN];
#pragma unroll
    for (int h = 0; h < WLEN; ++h) {
        xv[h] = xw[(size_t)h * EV4];
    }

    float4 mx = make_float4(-3.4e38f, -3.4e38f, -3.4e38f, -3.4e38f);

#pragma unroll
    for (int h = 0; h < WLEN; ++h) {
        float ax = bias, ay = bias, az = bias, aw_ = bias;
#pragma unroll
        for (int k = 0; k < 5; ++k) {
            int idx = h + k - 2;            // zero pad of 2: skip OOB taps
            if (idx >= 0 && idx < WLEN) {   // compile-time resolvable
                float wk = (k == 0) ? w0 : (k == 1) ? w1 : (k == 2) ? w2
                         : (k == 3) ? w3 : w4;
                ax  = fmaf(wk, xv[idx].x, ax);
                ay  = fmaf(wk, xv[idx].y, ay);
                az  = fmaf(wk, xv[idx].z, az);
                aw_ = fmaf(wk, xv[idx].w, aw_);
            }
        }
        mx.x = fmaxf(mx.x, ax);
        mx.y = fmaxf(mx.y, ay);
        mx.z = fmaxf(mx.z, az);
        mx.w = fmaxf(mx.w, aw_);
    }

    reinterpret_cast<float4*>(out)[(size_t)word * EV4 + lane_e] = mx;
}

extern "C" void kernel_launch(void* const* d_in, const int* in_sizes, int n_in,
                              void* d_out, int out_size)
{
    const float* x = (const float*)d_in[0];   // (B,S,W,E) = 41,943,040 floats
    const float* w = (const float*)d_in[1];   // 5 floats
    const float* b = (const float*)d_in[2];   // 1 float

    int n_words = in_sizes[0] / (WLEN * 128); // B*S = 16384

    int threads_total = n_words * EV4;        // 524288
    int block = 256;
    int grid  = (threads_total + block - 1) / block;

    cnn_conv_max_kernel<<<grid, block>>>(x, w, b, (float*)d_out, n_words);
}

// round 3
// speedup vs baseline: 1.0921x; 1.0921x over previous
#include <cuda_runtime.h>

// CNN char conv + max-pool over word length.
// x: (N=B*S, W=20, E=128) fp32, contiguous.
// conv: 5-tap FIR along W with zero pad 2, + bias, then max over W.
// out: (N, E) fp32.
//
// Persistent grid-stride version: grid sized to exactly fill the chip
// (148 SMs x 5 blocks), each 32-thread group loops over words. No wave
// transitions; next-word loads overlap current-word compute tail.
// Streaming cache hints (__ldcs/__stcs): zero-reuse data.

#define WLEN 20
#define EV4  32   // 128 floats / 4 per float4

__global__ __launch_bounds__(256, 5) void cnn_conv_max_kernel(
    const float* __restrict__ x,
    const float* __restrict__ w,
    const float* __restrict__ b,
    float* __restrict__ out,
    int n_words)
{
    const int lane_e = threadIdx.x & (EV4 - 1);
    const int group0 = (blockIdx.x * blockDim.x + threadIdx.x) >> 5;
    const int gstep  = (gridDim.x * blockDim.x) >> 5;

    // Weights/bias: 6 scalar loads, L1-resident after first iteration.
    const float w0 = w[0], w1 = w[1], w2 = w[2], w3 = w[3], w4 = w[4];
    const float bias = b[0];

    for (int word = group0; word < n_words; word += gstep) {
        const float4* xw = reinterpret_cast<const float4*>(x)
                         + (size_t)word * (WLEN * EV4) + lane_e;

        // Independent streaming loads; ptxas pipelines these.
        float4 xv[WLEN];
#pragma unroll
        for (int h = 0; h < WLEN; ++h) {
            xv[h] = __ldcs(&xw[(size_t)h * EV4]);
        }

        float4 mx = make_float4(-3.4e38f, -3.4e38f, -3.4e38f, -3.4e38f);

#pragma unroll
        for (int h = 0; h < WLEN; ++h) {
            float ax = bias, ay = bias, az = bias, aw_ = bias;
#pragma unroll
            for (int k = 0; k < 5; ++k) {
                int idx = h + k - 2;            // zero pad of 2: skip OOB taps
                if (idx >= 0 && idx < WLEN) {   // compile-time resolvable
                    float wk = (k == 0) ? w0 : (k == 1) ? w1 : (k == 2) ? w2
                             : (k == 3) ? w3 : w4;
                    ax  = fmaf(wk, xv[idx].x, ax);
                    ay  = fmaf(wk, xv[idx].y, ay);
                    az  = fmaf(wk, xv[idx].z, az);
                    aw_ = fmaf(wk, xv[idx].w, aw_);
                }
            }
            mx.x = fmaxf(mx.x, ax);
            mx.y = fmaxf(mx.y, ay);
            mx.z = fmaxf(mx.z, az);
            mx.w = fmaxf(mx.w, aw_);
        }

        __stcs(&reinterpret_cast<float4*>(out)[(size_t)word * EV4 + lane_e], mx);
    }
}

extern "C" void kernel_launch(void* const* d_in, const int* in_sizes, int n_in,
                              void* d_out, int out_size)
{
    const float* x = (const float*)d_in[0];   // (B,S,W,E)
    const float* w = (const float*)d_in[1];   // 5 floats
    const float* b = (const float*)d_in[2];   // 1 float

    int n_words = in_sizes[0] / (WLEN * 128); // B*S = 16384

    // Saturating persistent grid: 148 SMs x 5 blocks/SM.
    int block = 256;
    int grid  = 148 * 5;
    int max_grid = (n_words * EV4 + block - 1) / block;
    if (grid > max_grid) grid = max_grid;

    cnn_conv_max_kernel<<<grid, block>>>(x, w, b, (float*)d_out, n_words);
}